// round 12
// baseline (speedup 1.0000x reference)
#include <cuda_runtime.h>
#include <cuda_bf16.h>
#include <cstdint>

#define HW   1024
#define CD   128
#define EPSF 1e-8f
#define TQ   4            // q-tiles per CTA
#define STAGE_B 24576     // A(16KB) + B(8KB) per kc=32 stage
#define GS   65           // G buffer row stride (floats): bank = (m+n)&31

// Normalized features, bf16 hi/lo split, pixel-major:
// g_feat[view][p][0..127]=hi, [128..255]=lo   (512 B per pixel row)
__device__ __nv_bfloat16 g_feat[32 * HW * 256];

// ---------------------------------------------------------------------------
__device__ __forceinline__ uint32_t smem_u32(const void* p) {
    uint32_t a;
    asm("{ .reg .u64 t; cvta.to.shared.u64 t, %1; cvt.u32.u64 %0, t; }" : "=r"(a) : "l"(p));
    return a;
}

#define CP_ASYNC(s, g) \
    asm volatile("cp.async.cg.shared.global [%0], [%1], 16;" :: "r"(s), "l"(g))
#define CP_COMMIT() asm volatile("cp.async.commit_group;" ::: "memory")
#define CP_WAIT0()  asm volatile("cp.async.wait_group 0;" ::: "memory")

#define LDSM4(r, a) \
    asm volatile("ldmatrix.sync.aligned.m8n8.x4.shared.b16 {%0,%1,%2,%3}, [%4];" \
        : "=r"((r)[0]), "=r"((r)[1]), "=r"((r)[2]), "=r"((r)[3]) : "r"(a))

#define MMA(d, a, b0v, b1v)                                                  \
    asm volatile(                                                            \
        "mma.sync.aligned.m16n8k16.row.col.f32.bf16.bf16.f32 "               \
        "{%0,%1,%2,%3}, {%4,%5,%6,%7}, {%8,%9}, {%0,%1,%2,%3};\n"            \
        : "+f"((d)[0]), "+f"((d)[1]), "+f"((d)[2]), "+f"((d)[3])             \
        : "r"((a)[0]), "r"((a)[1]), "r"((a)[2]), "r"((a)[3]),                \
          "r"(b0v), "r"(b1v))

#define BAR_SYNC(id, cnt)   asm volatile("bar.sync %0, %1;"   :: "r"(id), "r"(cnt) : "memory")
#define BAR_ARRIVE(id, cnt) asm volatile("bar.arrive %0, %1;" :: "r"(id), "r"(cnt) : "memory")

// ---------------------------------------------------------------------------
// Kernel 1: L2-normalize per pixel, split to bf16 hi/lo, write pixel-major
// ---------------------------------------------------------------------------
__global__ __launch_bounds__(256) void norm_split_kernel(const float* __restrict__ x) {
    __shared__ uint32_t tile[8][33 * 32];
    int w = threadIdx.x >> 5, l = threadIdx.x & 31;
    int gp = blockIdx.x * 256 + w * 32 + l;        // global pixel over 32 views
    int view = gp >> 10, p = gp & 1023;
    const float* xp = x + (size_t)view * (CD * HW) + p;

    float s = 0.f;
#pragma unroll 8
    for (int c = 0; c < CD; ++c) { float v = xp[c << 10]; s += v * v; }
    float inv = 1.f / (sqrtf(s) + EPSF);

    __nv_bfloat16* ob = g_feat + (size_t)(gp - l) * 256;   // warp's base pixel row

    for (int cb = 0; cb < 4; ++cb) {
#pragma unroll
        for (int ci = 0; ci < 32; ++ci) {
            float v = xp[(cb * 32 + ci) << 10] * inv;
            __nv_bfloat16 h = __float2bfloat16(v);
            __nv_bfloat16 lo = __float2bfloat16(v - __bfloat162float(h));
            tile[w][ci * 33 + l] = (uint32_t)__bfloat16_as_ushort(h)
                                 | ((uint32_t)__bfloat16_as_ushort(lo) << 16);
        }
        __syncwarp();
#pragma unroll
        for (int rr = 0; rr < 32; ++rr) {
            uint32_t v = tile[w][l * 33 + rr];
            __nv_bfloat16* row = ob + (size_t)rr * 256 + cb * 32 + l;
            row[0]   = __ushort_as_bfloat16((unsigned short)(v & 0xFFFF));
            row[128] = __ushort_as_bfloat16((unsigned short)(v >> 16));
        }
        __syncwarp();
    }
}

// ---------------------------------------------------------------------------
// Kernel 2: warp-specialized HMMA GEMM over 48 unique view pairs.
// CTA = 192 thr: warps 0-3 compute (tile 128x64, warp 64x32, kc=32, 2-stage
// cp.async, persistent over TQ=4 q-tiles); warps 4-5 store. At tile end,
// compute drains acc -> G (128 x GS fp32, stride-65 => conflict-free rows,
// cols AND drain), bar-arrives, and continues MMAs while store warps write
// the direct tile to out[idx1] and the transposed twin to out[idx2].
// bar1 = G full (compute arrive / store sync), bar2 = G free (store arrive /
// compute sync), bar3 = compute-only mainloop barrier.
// smem = 2*24KB stages + 33.3KB G = 82KB -> 2 CTAs/SM.
// ---------------------------------------------------------------------------
__constant__ int c_pi[6] = {0, 0, 0, 1, 1, 2};
__constant__ int c_pj[6] = {1, 2, 3, 2, 3, 3};

__global__ __launch_bounds__(192, 2) void corr_gemm7(float* __restrict__ out) {
    extern __shared__ char smem[];
    uint32_t sb = smem_u32(smem);
    float* Gf = (float*)(smem + 2 * STAGE_B);

    const int tid = threadIdx.x;

    const int qg = blockIdx.x;                  // 0..3 -> q-tiles qg*4..+3
    const int p0 = blockIdx.y * 128;
    const int z  = blockIdx.z;                  // 0..47
    const int b  = z / 6, u = z % 6;
    const int i  = c_pi[u], j = c_pj[u];
    const int idx1 = b * 12 + i * 3 + (j - 1);
    const int idx2 = b * 12 + j * 3 + i;

    const char* Af  = (const char*)g_feat + (size_t)(b * 4 + j) * HW * 512 + (size_t)p0 * 512;
    const char* BfB = (const char*)g_feat + (size_t)(b * 4 + i) * HW * 512;

    if (tid < 128) {
        // ===================== compute warps (0-3) =========================
        const int w = tid >> 5, l = tid & 31;
        const int wm = w >> 1, wn = w & 1;      // warp grid 2x2
        const int lo16 = l & 15, hi2 = l >> 4;
        const int g = l >> 2, tg = l & 3;

        float acc[4][4][4];
#pragma unroll
        for (int mt = 0; mt < 4; ++mt)
#pragma unroll
            for (int nt = 0; nt < 4; ++nt)
#pragma unroll
                for (int e = 0; e < 4; ++e) acc[mt][nt][e] = 0.f;

        // stage loader: 1536 16B chunks (A 1024 + B 512), 12 per thread
        auto load_stage = [&](int s1) {
            int t = s1 >> 2, kcg = s1 & 3;
            uint32_t sbase = sb + (uint32_t)(s1 & 1) * STAGE_B;
            const char* Af2 = Af + kcg * 64;
            const char* Bf2 = BfB + (size_t)(qg * TQ + t) * 64 * 512 + kcg * 64;
#pragma unroll
            for (int it = 0; it < 12; ++it) {
                int c = it * 128 + tid;         // 0..1535
                if (c < 1024) {                 // A region
                    int m = c >> 3, half = (c >> 2) & 1, ch = c & 3;
                    uint32_t soff = half * 8192u
                                  + (uint32_t)((m * 4 + (ch ^ ((m >> 1) & 3))) << 4);
                    CP_ASYNC(sbase + soff, Af2 + (size_t)m * 512 + half * 256 + ch * 16);
                } else {                        // B region
                    int u2 = c - 1024;
                    int m = u2 >> 3, half = (u2 >> 2) & 1, ch = u2 & 3;
                    uint32_t soff = 16384u + half * 4096u
                                  + (uint32_t)((m * 4 + (ch ^ ((m >> 1) & 3))) << 4);
                    CP_ASYNC(sbase + soff, Bf2 + (size_t)m * 512 + half * 256 + ch * 16);
                }
            }
        };

        load_stage(0);
        CP_COMMIT();

        for (int s = 0; s < TQ * 4; ++s) {
            CP_WAIT0();
            BAR_SYNC(3, 128);
            if (s + 1 < TQ * 4) { load_stage(s + 1); CP_COMMIT(); }

            uint32_t st = sb + (uint32_t)(s & 1) * STAGE_B;
#pragma unroll
            for (int ks = 0; ks < 2; ++ks) {
                const int ch = ks * 2 + hi2;

                uint32_t ah[4][4], al[4][4], bb[2][4], swb[2];
#pragma unroll
                for (int mt = 0; mt < 4; ++mt) {
                    int m = wm * 64 + mt * 16 + lo16;
                    uint32_t sw = (uint32_t)((m * 4 + (ch ^ ((m >> 1) & 3))) << 4);
                    LDSM4(ah[mt], st + sw);
                    LDSM4(al[mt], st + 8192 + sw);
                }
#pragma unroll
                for (int np = 0; np < 2; ++np) {
                    int n = wn * 32 + np * 16 + lo16;
                    swb[np] = (uint32_t)((n * 4 + (ch ^ ((n >> 1) & 3))) << 4);
                    LDSM4(bb[np], st + 16384 + swb[np]);  // B_hi
                }
#pragma unroll
                for (int mt = 0; mt < 4; ++mt)
#pragma unroll
                    for (int nt = 0; nt < 4; ++nt)
                        MMA(acc[mt][nt], ah[mt], bb[nt >> 1][nt & 1], bb[nt >> 1][2 + (nt & 1)]);
#pragma unroll
                for (int mt = 0; mt < 4; ++mt)
#pragma unroll
                    for (int nt = 0; nt < 4; ++nt)
                        MMA(acc[mt][nt], al[mt], bb[nt >> 1][nt & 1], bb[nt >> 1][2 + (nt & 1)]);
#pragma unroll
                for (int np = 0; np < 2; ++np)
                    LDSM4(bb[np], st + 20480 + swb[np]);  // B_lo
#pragma unroll
                for (int mt = 0; mt < 4; ++mt)
#pragma unroll
                    for (int nt = 0; nt < 4; ++nt)
                        MMA(acc[mt][nt], ah[mt], bb[nt >> 1][nt & 1], bb[nt >> 1][2 + (nt & 1)]);
            }

            // ---- tile boundary: hand tile to store warps ----
            if ((s & 3) == 3) {
                int t = s >> 2;
                if (t > 0) BAR_SYNC(2, 192);    // wait: stores of t-1 done reading G
#pragma unroll
                for (int mt = 0; mt < 4; ++mt)
#pragma unroll
                    for (int nt = 0; nt < 4; ++nt)
#pragma unroll
                        for (int e = 0; e < 4; ++e) {
                            int m = wm * 64 + mt * 16 + g + 8 * (e >> 1);
                            int n = wn * 32 + nt * 8 + tg * 2 + (e & 1);
                            Gf[m * GS + n] = acc[mt][nt][e];
                            acc[mt][nt][e] = 0.f;
                        }
                BAR_ARRIVE(1, 192);             // G full -> release store warps
            }
        }
    } else {
        // ===================== store warps (4-5) ===========================
        const int t2 = tid - 128, sw = t2 >> 5, sl = t2 & 31;
        float* o1 = out + (size_t)idx1 * (HW * HW);
        float* o2 = out + (size_t)idx2 * (HW * HW);

        for (int t = 0; t < TQ; ++t) {
            BAR_SYNC(1, 192);                   // wait: G full
            int qp0 = (qg * TQ + t) * 64;

            // direct: out[idx1], warp per row, 2 warps cover 128 rows
#pragma unroll 4
            for (int it = 0; it < 64; ++it) {
                int r = it * 2 + sw;
                float v0 = Gf[r * GS + sl];
                float v1 = Gf[r * GS + sl + 32];
                float* orow = &o1[(size_t)(p0 + r) * HW + qp0];
                orow[sl]      = v0;
                orow[sl + 32] = v1;
            }
            // transposed: out[idx2] rows n = G columns (bank=(m+n)&31: clean)
#pragma unroll 4
            for (int nn = 0; nn < 32; ++nn) {
                int n = sw * 32 + nn;
                float* orow = &o2[(size_t)(qp0 + n) * HW + p0];
#pragma unroll
                for (int k = 0; k < 4; ++k)
                    orow[32 * k + sl] = Gf[(32 * k + sl) * GS + n];
            }

            if (t < TQ - 1) BAR_ARRIVE(2, 192); // G free
        }
    }
}

// ---------------------------------------------------------------------------
extern "C" void kernel_launch(void* const* d_in, const int* in_sizes, int n_in,
                              void* d_out, int out_size) {
    const float* x = (const float*)d_in[0];
    float* out = (float*)d_out;

    norm_split_kernel<<<128, 256>>>(x);

    int smem_sz = 2 * STAGE_B + 128 * GS * 4;   // 82432 B
    cudaFuncSetAttribute(corr_gemm7, cudaFuncAttributeMaxDynamicSharedMemorySize, smem_sz);
    dim3 grid(16 / TQ, 8, 48);
    corr_gemm7<<<grid, 192, smem_sz>>>(out);
}

// round 13
// speedup vs baseline: 1.1032x; 1.1032x over previous
#include <cuda_runtime.h>
#include <cuda_bf16.h>
#include <cstdint>

#define HW   1024
#define CD   128
#define EPSF 1e-8f
#define TQ   4            // q-tiles per CTA
#define STAGE_B 24576     // A(16KB) + B(8KB) per kc=32 stage
#define TW_OFF  49152     // dedicated per-warp transpose buffers (4 x 2KB)

// Normalized features, bf16 hi/lo split, pixel-major:
// g_feat[view][p][0..127]=hi, [128..255]=lo   (512 B per pixel row)
__device__ __nv_bfloat16 g_feat[32 * HW * 256];

// ---------------------------------------------------------------------------
__device__ __forceinline__ uint32_t smem_u32(const void* p) {
    uint32_t a;
    asm("{ .reg .u64 t; cvta.to.shared.u64 t, %1; cvt.u32.u64 %0, t; }" : "=r"(a) : "l"(p));
    return a;
}

#define CP_ASYNC(s, g) \
    asm volatile("cp.async.cg.shared.global [%0], [%1], 16;" :: "r"(s), "l"(g))
#define CP_COMMIT() asm volatile("cp.async.commit_group;" ::: "memory")
#define CP_WAIT0()  asm volatile("cp.async.wait_group 0;" ::: "memory")

#define LDSM4(r, a) \
    asm volatile("ldmatrix.sync.aligned.m8n8.x4.shared.b16 {%0,%1,%2,%3}, [%4];" \
        : "=r"((r)[0]), "=r"((r)[1]), "=r"((r)[2]), "=r"((r)[3]) : "r"(a))

#define MMA(d, a, b0v, b1v)                                                  \
    asm volatile(                                                            \
        "mma.sync.aligned.m16n8k16.row.col.f32.bf16.bf16.f32 "               \
        "{%0,%1,%2,%3}, {%4,%5,%6,%7}, {%8,%9}, {%0,%1,%2,%3};\n"            \
        : "+f"((d)[0]), "+f"((d)[1]), "+f"((d)[2]), "+f"((d)[3])             \
        : "r"((a)[0]), "r"((a)[1]), "r"((a)[2]), "r"((a)[3]),                \
          "r"(b0v), "r"(b1v))

// ---------------------------------------------------------------------------
// Kernel 1: L2-normalize per pixel, split to bf16 hi/lo, write pixel-major
// ---------------------------------------------------------------------------
__global__ __launch_bounds__(256) void norm_split_kernel(const float* __restrict__ x) {
    __shared__ uint32_t tile[8][33 * 32];
    int w = threadIdx.x >> 5, l = threadIdx.x & 31;
    int gp = blockIdx.x * 256 + w * 32 + l;        // global pixel over 32 views
    int view = gp >> 10, p = gp & 1023;
    const float* xp = x + (size_t)view * (CD * HW) + p;

    float s = 0.f;
#pragma unroll 8
    for (int c = 0; c < CD; ++c) { float v = xp[c << 10]; s += v * v; }
    float inv = 1.f / (sqrtf(s) + EPSF);

    __nv_bfloat16* ob = g_feat + (size_t)(gp - l) * 256;   // warp's base pixel row

    for (int cb = 0; cb < 4; ++cb) {
#pragma unroll
        for (int ci = 0; ci < 32; ++ci) {
            float v = xp[(cb * 32 + ci) << 10] * inv;
            __nv_bfloat16 h = __float2bfloat16(v);
            __nv_bfloat16 lo = __float2bfloat16(v - __bfloat162float(h));
            tile[w][ci * 33 + l] = (uint32_t)__bfloat16_as_ushort(h)
                                 | ((uint32_t)__bfloat16_as_ushort(lo) << 16);
        }
        __syncwarp();
#pragma unroll
        for (int rr = 0; rr < 32; ++rr) {
            uint32_t v = tile[w][l * 33 + rr];
            __nv_bfloat16* row = ob + (size_t)rr * 256 + cb * 32 + l;
            row[0]   = __ushort_as_bfloat16((unsigned short)(v & 0xFFFF));
            row[128] = __ushort_as_bfloat16((unsigned short)(v >> 16));
        }
        __syncwarp();
    }
}

// ---------------------------------------------------------------------------
// Kernel 2: HMMA GEMM over 48 unique view pairs; CTA tile 128x64 (4 warps,
// warp 64x32), kc=32, 2-stage cp.async, persistent over TQ=4 q-tiles with a
// CONTINUOUS stage stream across tile boundaries (loads overlap epilogues).
// Per-tile epilogue is warp-local (no block barriers): direct stores from
// regs to out[idx1]; transposed twin to out[idx2] via dedicated per-warp
// 2KB smem in 4 sub-rounds (rotation addressing, ~conflict-free).
// smem = 2*24KB stages + 8KB tw = 56KB -> 4 CTAs/SM.
// ---------------------------------------------------------------------------
__constant__ int c_pi[6] = {0, 0, 0, 1, 1, 2};
__constant__ int c_pj[6] = {1, 2, 3, 2, 3, 3};

__global__ __launch_bounds__(128, 4) void corr_gemm8(float* __restrict__ out) {
    extern __shared__ char smem[];
    uint32_t sb = smem_u32(smem);
    const int tid = threadIdx.x;
    const int w = tid >> 5, l = tid & 31;
    const int wm = w >> 1, wn = w & 1;          // warp grid 2x2
    const int lo16 = l & 15, hi2 = l >> 4;
    const int g = l >> 2, tg = l & 3;

    const int qg = blockIdx.x;                  // 0..3 -> q-tiles qg*4..+3
    const int p0 = blockIdx.y * 128;
    const int z  = blockIdx.z;                  // 0..47
    const int b  = z / 6, u = z % 6;
    const int i  = c_pi[u], j = c_pj[u];
    const int idx1 = b * 12 + i * 3 + (j - 1);
    const int idx2 = b * 12 + j * 3 + i;

    const char* Af  = (const char*)g_feat + (size_t)(b * 4 + j) * HW * 512 + (size_t)p0 * 512;
    const char* BfB = (const char*)g_feat + (size_t)(b * 4 + i) * HW * 512;
    float* o1 = out + (size_t)idx1 * (HW * HW);
    float* o2 = out + (size_t)idx2 * (HW * HW);

    float acc[4][4][4];
#pragma unroll
    for (int mt = 0; mt < 4; ++mt)
#pragma unroll
        for (int nt = 0; nt < 4; ++nt)
#pragma unroll
            for (int e = 0; e < 4; ++e) acc[mt][nt][e] = 0.f;

    // ---- stage loader, global stage index s1 = tile*4 + kc ----
    auto load_stage = [&](int s1) {
        int t = s1 >> 2, kcg = s1 & 3;
        uint32_t sbase = sb + (uint32_t)(s1 & 1) * STAGE_B;
        const char* Af2 = Af + kcg * 64;
        const char* Bf2 = BfB + (size_t)(qg * TQ + t) * 64 * 512 + kcg * 64;
#pragma unroll
        for (int it = 0; it < 12; ++it) {
            int c = it * 128 + tid;             // 0..1535
            if (c < 1024) {                     // A region
                int m = c >> 3, half = (c >> 2) & 1, ch = c & 3;
                uint32_t soff = half * 8192u
                              + (uint32_t)((m * 4 + (ch ^ ((m >> 1) & 3))) << 4);
                CP_ASYNC(sbase + soff, Af2 + (size_t)m * 512 + half * 256 + ch * 16);
            } else {                            // B region
                int u2 = c - 1024;
                int m = u2 >> 3, half = (u2 >> 2) & 1, ch = u2 & 3;
                uint32_t soff = 16384u + half * 4096u
                              + (uint32_t)((m * 4 + (ch ^ ((m >> 1) & 3))) << 4);
                CP_ASYNC(sbase + soff, Bf2 + (size_t)m * 512 + half * 256 + ch * 16);
            }
        }
    };

    load_stage(0);
    CP_COMMIT();

    float* tw = (float*)(smem + TW_OFF) + w * 512;   // per-warp 2KB (8 rows x 64)

    for (int t = 0; t < TQ; ++t) {
        for (int kc = 0; kc < 4; ++kc) {
            int s = t * 4 + kc;
            CP_WAIT0();
            __syncthreads();
            if (s + 1 < TQ * 4) { load_stage(s + 1); CP_COMMIT(); }

            uint32_t st = sb + (uint32_t)(s & 1) * STAGE_B;
#pragma unroll
            for (int ks = 0; ks < 2; ++ks) {
                const int ch = ks * 2 + hi2;

                uint32_t ah[4][4], al[4][4], bb[2][4], swb[2];
#pragma unroll
                for (int mt = 0; mt < 4; ++mt) {
                    int m = wm * 64 + mt * 16 + lo16;
                    uint32_t sw = (uint32_t)((m * 4 + (ch ^ ((m >> 1) & 3))) << 4);
                    LDSM4(ah[mt], st + sw);
                    LDSM4(al[mt], st + 8192 + sw);
                }
#pragma unroll
                for (int np = 0; np < 2; ++np) {
                    int n = wn * 32 + np * 16 + lo16;
                    swb[np] = (uint32_t)((n * 4 + (ch ^ ((n >> 1) & 3))) << 4);
                    LDSM4(bb[np], st + 16384 + swb[np]);  // B_hi
                }
#pragma unroll
                for (int mt = 0; mt < 4; ++mt)
#pragma unroll
                    for (int nt = 0; nt < 4; ++nt)
                        MMA(acc[mt][nt], ah[mt], bb[nt >> 1][nt & 1], bb[nt >> 1][2 + (nt & 1)]);
#pragma unroll
                for (int mt = 0; mt < 4; ++mt)
#pragma unroll
                    for (int nt = 0; nt < 4; ++nt)
                        MMA(acc[mt][nt], al[mt], bb[nt >> 1][nt & 1], bb[nt >> 1][2 + (nt & 1)]);
#pragma unroll
                for (int np = 0; np < 2; ++np)
                    LDSM4(bb[np], st + 20480 + swb[np]);  // B_lo
#pragma unroll
                for (int mt = 0; mt < 4; ++mt)
#pragma unroll
                    for (int nt = 0; nt < 4; ++nt)
                        MMA(acc[mt][nt], ah[mt], bb[nt >> 1][nt & 1], bb[nt >> 1][2 + (nt & 1)]);
            }
        }

        // ================= warp-local epilogue for tile t ==================
        int qp0 = (qg * TQ + t) * 64;

        // direct: out[idx1] from regs (float2, coalesced)
#pragma unroll
        for (int mt = 0; mt < 4; ++mt) {
#pragma unroll
            for (int nt = 0; nt < 4; ++nt) {
                int row = p0 + wm * 64 + mt * 16 + g;
                int col = qp0 + wn * 32 + nt * 8 + tg * 2;
                *(float2*)&o1[(size_t)row * HW + col] =
                    make_float2(acc[mt][nt][0], acc[mt][nt][1]);
                *(float2*)&o1[(size_t)(row + 8) * HW + col] =
                    make_float2(acc[mt][nt][2], acc[mt][nt][3]);
            }
        }

        // transposed: out[idx2] via per-warp tw, 4 sub-rounds of 8 n-rows
#pragma unroll
        for (int nt = 0; nt < 4; ++nt) {
#pragma unroll
            for (int mt = 0; mt < 4; ++mt)
#pragma unroll
                for (int e = 0; e < 4; ++e) {
                    int nr = tg * 2 + (e & 1);                    // 0..7
                    int m  = mt * 16 + g + 8 * (e >> 1);          // 0..63
                    tw[nr * 64 + ((m + 8 * nr) & 63)] = acc[mt][nt][e];
                }
            __syncwarp();
#pragma unroll
            for (int nr = 0; nr < 8; ++nr) {
                int n = wn * 32 + nt * 8 + nr;
                int x = (2 * l + 8 * nr) & 63;
                float2 v = *(float2*)&tw[nr * 64 + x];            // (G[n][2l],G[n][2l+1])
                *(float2*)&o2[(size_t)(qp0 + n) * HW + p0 + wm * 64 + 2 * l] = v;
            }
            __syncwarp();
        }

        // reset acc for next tile
#pragma unroll
        for (int mt = 0; mt < 4; ++mt)
#pragma unroll
            for (int nt = 0; nt < 4; ++nt)
#pragma unroll
                for (int e = 0; e < 4; ++e) acc[mt][nt][e] = 0.f;
    }
}

// ---------------------------------------------------------------------------
extern "C" void kernel_launch(void* const* d_in, const int* in_sizes, int n_in,
                              void* d_out, int out_size) {
    const float* x = (const float*)d_in[0];
    float* out = (float*)d_out;

    norm_split_kernel<<<128, 256>>>(x);

    int smem_sz = TW_OFF + 8192;   // 56 KB
    cudaFuncSetAttribute(corr_gemm8, cudaFuncAttributeMaxDynamicSharedMemorySize, smem_sz);
    dim3 grid(16 / TQ, 8, 48);
    corr_gemm8<<<grid, 128, smem_sz>>>(out);
}